// round 6
// baseline (speedup 1.0000x reference)
#include <cuda_runtime.h>
#include <math.h>

#define Bv 32
#define Sv 2048
#define Ev 1024
#define Dv 1024

// Scratch (no device allocations, no atomics)
__device__ float g_pp [Bv * 128];          // hp partials per (batch, itile)
__device__ float g_qp [16][Bv * Ev];       // q partials per d-chunk
__device__ float g_c  [Bv];
__device__ float g_att[Bv * Sv];

__device__ __forceinline__ float warp_sum(float v) {
#pragma unroll
    for (int o = 16; o > 0; o >>= 1) v += __shfl_xor_sync(0xffffffffu, v, o);
    return v;
}

// ---------------------------------------------------------------------------
// k_hp (side stream): warp per i, 8 batches per block, 512 blocks.
// ---------------------------------------------------------------------------
__global__ void k_hp(const float* __restrict__ h,
                     const float* __restrict__ Wp_w,
                     const float* __restrict__ Wp_b,
                     const float* __restrict__ vp_w) {
    __shared__ float4 hs4[8][Dv / 4];     // 32 KB
    __shared__ float wtmp[8][8];
    int t = threadIdx.x;
    int b0 = (blockIdx.x >> 7) * 8;
    int itile = blockIdx.x & 127;
    for (int idx = t; idx < 8 * (Dv / 4); idx += 256) {
        int k = idx >> 8, j = idx & 255;
        hs4[k][j] = ((const float4*)(h + (size_t)(b0 + k) * Dv))[j];
    }
    __syncthreads();
    int w = t >> 5, lane = t & 31;
    int i = itile * 8 + w;
    const float4* wr = (const float4*)(Wp_w + (size_t)i * Dv);
    float acc[8];
#pragma unroll
    for (int k = 0; k < 8; k++) acc[k] = 0.f;
#pragma unroll
    for (int j = lane; j < Dv / 4; j += 32) {
        float4 wv = wr[j];
#pragma unroll
        for (int k = 0; k < 8; k++) {
            float4 x = hs4[k][j];
            acc[k] += wv.x * x.x + wv.y * x.y + wv.z * x.z + wv.w * x.w;
        }
    }
#pragma unroll
    for (int k = 0; k < 8; k++) acc[k] = warp_sum(acc[k]);
    if (lane == 0) {
        float bia = Wp_b[i];
        float vp  = vp_w[i];
#pragma unroll
        for (int k = 0; k < 8; k++) wtmp[w][k] = tanhf(acc[k] + bia) * vp;
    }
    __syncthreads();
    if (t < 8) {
        float s = 0.f;
#pragma unroll
        for (int w2 = 0; w2 < 8; w2++) s += wtmp[w2][t];
        g_pp[(b0 + t) * 128 + itile] = s;
    }
}

// ---------------------------------------------------------------------------
// k_q: 160 blocks. [0,128): q partials (row-major Wa_w). [128,160): c[b].
// ---------------------------------------------------------------------------
__global__ void k_q(const float* __restrict__ h,
                    const float* __restrict__ Wa_w,
                    const float* __restrict__ Wa_b) {
    int bid = blockIdx.x, t = threadIdx.x;
    if (bid < 128) {
        __shared__ float hs[4][64];
        int dc = bid >> 3;                // 16 chunks of 64 d-rows
        int bg = bid & 7;                 // 8 groups of 4 batches
        int b0 = bg * 4, d0 = dc * 64;
        if (t < 256) {
            int k = t >> 6, d = t & 63;
            hs[k][d] = h[(size_t)(b0 + k) * Dv + d0 + d];
        }
        __syncthreads();
        float4 a0 = make_float4(0.f,0.f,0.f,0.f), a1 = a0, a2 = a0, a3 = a0;
#pragma unroll 4
        for (int d = 0; d < 64; d++) {
            float4 wv = ((const float4*)(Wa_w + (size_t)(d0 + d) * Ev))[t];
            float x0 = hs[0][d], x1 = hs[1][d], x2 = hs[2][d], x3 = hs[3][d];
            a0.x += wv.x*x0; a0.y += wv.y*x0; a0.z += wv.z*x0; a0.w += wv.w*x0;
            a1.x += wv.x*x1; a1.y += wv.y*x1; a1.z += wv.z*x1; a1.w += wv.w*x1;
            a2.x += wv.x*x2; a2.y += wv.y*x2; a2.z += wv.z*x2; a2.w += wv.w*x2;
            a3.x += wv.x*x3; a3.y += wv.y*x3; a3.z += wv.z*x3; a3.w += wv.w*x3;
        }
        ((float4*)(g_qp[dc] + (b0 + 0) * Ev))[t] = a0;
        ((float4*)(g_qp[dc] + (b0 + 1) * Ev))[t] = a1;
        ((float4*)(g_qp[dc] + (b0 + 2) * Ev))[t] = a2;
        ((float4*)(g_qp[dc] + (b0 + 3) * Ev))[t] = a3;
    } else {
        int b = bid - 128;
        float v = 0.f;
        for (int d = t; d < Dv; d += 256) v += h[b * Dv + d] * Wa_b[d];
        v = warp_sum(v);
        __shared__ float red[8];
        if ((t & 31) == 0) red[t >> 5] = v;
        __syncthreads();
        if (t == 0) {
            float s = 0.f;
#pragma unroll
            for (int i = 0; i < 8; i++) s += red[i];
            g_c[b] = s;
        }
    }
}

// ---------------------------------------------------------------------------
// k_att: grid (32 tiles, 32 batches). 2 rows per warp-iteration -> 16 loads
// in flight per warp; reduces the 16 q-partials into smem first.
// ---------------------------------------------------------------------------
__global__ void k_att(const float* __restrict__ enc) {
    __shared__ float4 qs[Ev / 4];
    int tile = blockIdx.x, b = blockIdx.y, t = threadIdx.x;

    for (int j = t; j < Ev; j += 256) {
        float s = 0.f;
#pragma unroll
        for (int dc = 0; dc < 16; dc++) s += g_qp[dc][b * Ev + j];
        ((float*)qs)[j] = s;
    }
    __syncthreads();

    int w = t >> 5, lane = t & 31;
    float c = g_c[b];
#pragma unroll
    for (int r = 0; r < 8; r += 2) {
        int s = tile * 64 + w * 8 + r;
        const float4* er0 = (const float4*)(enc + ((size_t)b * Sv + s)     * Ev);
        const float4* er1 = (const float4*)(enc + ((size_t)b * Sv + s + 1) * Ev);
        float acc0 = 0.f, acc1 = 0.f;
#pragma unroll
        for (int j = lane; j < Ev / 4; j += 32) {
            float4 x  = qs[j];
            float4 a0 = __ldcs(er0 + j);
            float4 a1 = __ldcs(er1 + j);
            acc0 += a0.x * x.x + a0.y * x.y + a0.z * x.z + a0.w * x.w;
            acc1 += a1.x * x.x + a1.y * x.y + a1.z * x.z + a1.w * x.w;
        }
        acc0 = warp_sum(acc0);
        acc1 = warp_sum(acc1);
        if (lane == 0) {
            g_att[b * Sv + s]     = acc0 + c;
            g_att[b * Sv + s + 1] = acc1 + c;
        }
    }
}

// ---------------------------------------------------------------------------
// k_fin: grid (8 e-tiles, 32 batches), 1024 threads.
//   Every block redundantly computes p + softmax stats (fast, L2-hot);
//   e-tile 0 writes alpha; each block computes a 128-col slice of the
//   windowed awe (8x latency-hiding parallelism vs 1 block/batch).
// ---------------------------------------------------------------------------
__global__ void k_fin(const float* __restrict__ enc, float* __restrict__ awe,
                      float* __restrict__ alpha, const float* __restrict__ vp_b) {
    int tile = blockIdx.x, b = blockIdx.y, t = threadIdx.x;
    int lane = t & 31, wrp = t >> 5;
    __shared__ float red[128];
    __shared__ float fin, shp;
    __shared__ float aw[128];
    __shared__ float4 pacc[32][32];        // 16 KB

    // p[b] from g_pp partials (redundant per tile)
    if (t < 128) red[t] = g_pp[b * 128 + t];
    __syncthreads();
    for (int o = 64; o > 0; o >>= 1) {
        if (t < o) red[t] += red[t + o];
        __syncthreads();
    }
    if (t == 0) {
        float x = red[0] + vp_b[0];
        shp = (float)Sv / (1.f + expf(-x));
    }
    __syncthreads();
    float p = shp;
    int lo = (int)floorf(p) - 64;
    if (lo < 0) lo = 0;
    if (lo > Sv - 128) lo = Sv - 128;

    // softmax stats (redundant per tile; att is L2-hot)
    float a0 = g_att[b * Sv + t];
    float a1 = g_att[b * Sv + t + 1024];
    float m = fmaxf(a0, a1);
#pragma unroll
    for (int o = 16; o > 0; o >>= 1) m = fmaxf(m, __shfl_xor_sync(0xffffffffu, m, o));
    if (lane == 0) red[wrp] = m;
    __syncthreads();
    if (wrp == 0) {
        float v = red[lane];
#pragma unroll
        for (int o = 16; o > 0; o >>= 1) v = fmaxf(v, __shfl_xor_sync(0xffffffffu, v, o));
        if (lane == 0) fin = v;
    }
    __syncthreads();
    float mb = fin;
    float e0 = expf(a0 - mb), e1 = expf(a1 - mb);
    float l = warp_sum(e0 + e1);
    __syncthreads();
    if (lane == 0) red[wrp] = l;
    __syncthreads();
    if (wrp == 0) {
        float v = red[lane];
        v = warp_sum(v);
        if (lane == 0) fin = v;
    }
    __syncthreads();
    float inv = 1.f / fin;
    float d0 = (float)t - p, d1 = (float)(t + 1024) - p;
    float al0 = e0 * inv * expf(-d0 * d0 * 0.125f);
    float al1 = e1 * inv * expf(-d1 * d1 * 0.125f);
    if (tile == 0) {
        alpha[b * Sv + t]        = al0;
        alpha[b * Sv + t + 1024] = al1;
    }
    int w0 = t - lo, w1 = t + 1024 - lo;
    if ((unsigned)w0 < 128u) aw[w0] = al0;
    if ((unsigned)w1 < 128u) aw[w1] = al1;
    __syncthreads();

    // windowed awe for this block's 128-col slice; alpha outside |s-p|<=29 is
    // exactly 0 (fp32 underflow, identical in the reference) -> skip loads.
    int c4 = t & 31;                       // float4 col within the tile slice
    int sg = t >> 5;                       // 32 s-groups of 4 rows
    float4 acc = make_float4(0.f, 0.f, 0.f, 0.f);
    const float4* base = (const float4*)(enc + ((size_t)b * Sv + lo) * Ev)
                         + tile * 32;      // slice offset (128 floats)
#pragma unroll
    for (int i = 0; i < 4; i++) {
        int sl = sg * 4 + i;
        float a = aw[sl];
        if (a != 0.f) {
            float4 v = base[(size_t)sl * (Ev / 4) + c4];
            acc.x += v.x * a; acc.y += v.y * a; acc.z += v.z * a; acc.w += v.w * a;
        }
    }
    pacc[sg][c4] = acc;
    __syncthreads();
#pragma unroll
    for (int o = 16; o > 0; o >>= 1) {
        if (sg < o) {
            float4 u = pacc[sg][c4], v = pacc[sg + o][c4];
            u.x += v.x; u.y += v.y; u.z += v.z; u.w += v.w;
            pacc[sg][c4] = u;
        }
        __syncthreads();
    }
    if (t < 32)
        ((float4*)(awe + b * Ev + tile * 128))[t] = pacc[0][t];
}

extern "C" void kernel_launch(void* const* d_in, const int* in_sizes, int n_in,
                              void* d_out, int out_size) {
    const float* enc  = (const float*)d_in[0];   // [B,S,E]
    const float* h    = (const float*)d_in[1];   // [B,D]
    const float* Wa_w = (const float*)d_in[3];   // [D,E]
    const float* Wa_b = (const float*)d_in[4];   // [D]
    const float* Wp_w = (const float*)d_in[5];   // [D,D]
    const float* Wp_b = (const float*)d_in[6];   // [D]
    const float* vp_w = (const float*)d_in[7];   // [1,D]
    const float* vp_b = (const float*)d_in[8];   // [1]

    float* awe   = (float*)d_out;                 // [B,E]
    float* alpha = (float*)d_out + Bv * Ev;       // [B,S]

    // Fork-join: k_hp on a side stream, overlapped with k_q -> k_att.
    cudaStream_t s1;
    cudaStreamCreateWithFlags(&s1, cudaStreamNonBlocking);
    cudaEvent_t evFork, evJoin;
    cudaEventCreateWithFlags(&evFork, cudaEventDisableTiming);
    cudaEventCreateWithFlags(&evJoin, cudaEventDisableTiming);

    cudaEventRecord(evFork, 0);
    cudaStreamWaitEvent(s1, evFork, 0);

    k_hp<<<512, 256, 0, s1>>>(h, Wp_w, Wp_b, vp_w);   // side stream

    k_q  <<<160, 256>>>(h, Wa_w, Wa_b);               // main stream
    k_att<<<dim3(32, Bv), 256>>>(enc);

    cudaEventRecord(evJoin, s1);
    cudaStreamWaitEvent(0, evJoin, 0);

    k_fin<<<dim3(8, Bv), 1024>>>(enc, awe, alpha, vp_b);
}